// round 8
// baseline (speedup 1.0000x reference)
#include <cuda_runtime.h>
#include <cstdint>

#define RKHS 20
#define OUTD 128
#define TILE 128   // rows per tile == threads per block

// Fast cos: Cody-Waite 2-term reduction by 2*pi, then MUFU cos (|r|<=pi).
__device__ __forceinline__ float fast_cos(float x) {
    const float INV_2PI   = 0.15915494309189535f;
    const float TWO_PI_HI = 6.28318548202514648f;
    const float TWO_PI_LO = -1.7484556e-7f;
    float k = rintf(x * INV_2PI);
    float r = fmaf(-k, TWO_PI_HI, x);
    r = fmaf(-k, TWO_PI_LO, r);
    return __cosf(r);
}

// Packed fp32x2 FMA (Blackwell FFMA2) — one issue, two FMAs.
__device__ __forceinline__ void ffma2(unsigned long long& acc,
                                      unsigned long long a,
                                      unsigned long long b) {
    asm("fma.rn.f32x2 %0, %1, %2, %3;" : "=l"(acc) : "l"(a), "l"(b), "l"(acc));
}

__device__ __forceinline__ float unpack_add(unsigned long long v) {
    unsigned lo, hi;
    asm("mov.b64 {%0,%1}, %2;" : "=r"(lo), "=r"(hi) : "l"(v));
    return __uint_as_float(lo) + __uint_as_float(hi);
}

// Two-phase tile kernel.
// Phase A: thread i stages row i's KDE vector (if masked) into smem.
// Phase B: one warp per row; lane l owns cols [4l,4l+4). Matvec uses packed
//          f32x2 FMAs: k-pairs come packed straight from LDS.128, weights
//          pre-packed in registers, accumulators packed over k-parity.
__global__ __launch_bounds__(TILE, 4) void kde_time_encoder_kernel(
    const float* __restrict__ t_diff,
    const int* __restrict__ kde_idx,
    const int* __restrict__ kde_mask,
    const float* __restrict__ kde_table,
    const float* __restrict__ W_proj,
    const float* __restrict__ b_proj,
    const float* __restrict__ W_fb,
    const float* __restrict__ b_fb,
    float* __restrict__ out,
    int n)
{
    __shared__ __align__(16) float sk[TILE * RKHS];  // 10 KB staged KDE vecs
    __shared__ float st[TILE];
    __shared__ int   sm[TILE];

    const int tid   = threadIdx.x;
    const int lane  = tid & 31;
    const int wid   = tid >> 5;
    const int obase = lane * 4;

    // Pre-pack this lane's weights: wp[j][i] = (w_j[2i], w_j[2i+1]).
    unsigned long long wp[4][RKHS / 2];
    unsigned long long bpp[4];    // (bias, 0) packed accumulator init
    float wf[4], bf[4];
#pragma unroll
    for (int j = 0; j < 4; j++) {
        const float* wrow = W_proj + (obase + j) * RKHS;
#pragma unroll
        for (int i = 0; i < RKHS / 2; i++) {
            unsigned lo = __float_as_uint(wrow[2 * i]);
            unsigned hi = __float_as_uint(wrow[2 * i + 1]);
            wp[j][i] = (unsigned long long)lo | ((unsigned long long)hi << 32);
        }
        bpp[j] = (unsigned long long)__float_as_uint(b_proj[obase + j]); // hi = 0.0f
        wf[j] = W_fb[obase + j];
        bf[j] = b_fb[obase + j];
    }

    const int ntiles = (n + TILE - 1) / TILE;

    for (int tile = blockIdx.x; tile < ntiles; tile += gridDim.x) {
        const int base = tile * TILE;
        const int row  = base + tid;

        // ---- Phase A: stage tile ----
        int   m  = 0;
        float tv = 0.0f;
        if (row < n) {
            m  = kde_mask[row];
            tv = t_diff[row];
        }
        sm[tid] = m;
        st[tid] = tv;
        if (m) {
            const float4* kv = reinterpret_cast<const float4*>(
                kde_table + (size_t)kde_idx[row] * RKHS);
            float4 v0 = kv[0], v1 = kv[1], v2 = kv[2], v3 = kv[3], v4 = kv[4];
            float4* dstp = reinterpret_cast<float4*>(sk + tid * RKHS);
            dstp[0] = v0; dstp[1] = v1; dstp[2] = v2; dstp[3] = v3; dstp[4] = v4;
        }
        __syncthreads();

        // ---- Phase B: warp per row ----
        const int nrows = min(TILE, n - base);
        for (int r = wid; r < nrows; r += 4) {
            float4 res;
            if (sm[r]) {                       // warp-uniform branch
                // 80B = 5 x LDS.128; each yields 2 packed k-pairs.
                const ulonglong2* kk = reinterpret_cast<const ulonglong2*>(sk + r * RKHS);
                unsigned long long a0 = bpp[0], a1 = bpp[1], a2 = bpp[2], a3 = bpp[3];
#pragma unroll
                for (int q = 0; q < 5; q++) {
                    ulonglong2 kp = kk[q];     // (k[4q],k[4q+1]) , (k[4q+2],k[4q+3])
                    ffma2(a0, kp.x, wp[0][2 * q]);
                    ffma2(a1, kp.x, wp[1][2 * q]);
                    ffma2(a2, kp.x, wp[2][2 * q]);
                    ffma2(a3, kp.x, wp[3][2 * q]);
                    ffma2(a0, kp.y, wp[0][2 * q + 1]);
                    ffma2(a1, kp.y, wp[1][2 * q + 1]);
                    ffma2(a2, kp.y, wp[2][2 * q + 1]);
                    ffma2(a3, kp.y, wp[3][2 * q + 1]);
                }
                res.x = unpack_add(a0);
                res.y = unpack_add(a1);
                res.z = unpack_add(a2);
                res.w = unpack_add(a3);
            } else {
                float t = st[r];
                res.x = fast_cos(fmaf(t, wf[0], bf[0]));
                res.y = fast_cos(fmaf(t, wf[1], bf[1]));
                res.z = fast_cos(fmaf(t, wf[2], bf[2]));
                res.w = fast_cos(fmaf(t, wf[3], bf[3]));
            }
            __stcs(reinterpret_cast<float4*>(out + (size_t)(base + r) * OUTD) + lane, res);
        }
        __syncthreads();  // protect smem before next tile
    }
}

extern "C" void kernel_launch(void* const* d_in, const int* in_sizes, int n_in,
                              void* d_out, int out_size)
{
    // metadata order: src, dst, t_diff, kde_idx, kde_mask, kde_table,
    //                 W_proj, b_proj, W_fb, b_fb
    const float* t_diff    = (const float*)d_in[2];
    const int*   kde_idx   = (const int*)d_in[3];
    const int*   kde_mask  = (const int*)d_in[4];
    const float* kde_table = (const float*)d_in[5];
    const float* W_proj    = (const float*)d_in[6];
    const float* b_proj    = (const float*)d_in[7];
    const float* W_fb      = (const float*)d_in[8];
    const float* b_fb      = (const float*)d_in[9];
    float*       out       = (float*)d_out;

    const int n = in_sizes[2];  // BATCH

    kde_time_encoder_kernel<<<1184, TILE>>>(
        t_diff, kde_idx, kde_mask, kde_table, W_proj, b_proj, W_fb, b_fb, out, n);
}

// round 11
// speedup vs baseline: 1.1017x; 1.1017x over previous
#include <cuda_runtime.h>
#include <cstdint>

#define RKHS 20
#define OUTD 128
#define TILE 128   // rows per tile == threads per block

// ---------- cp.async helpers ----------
__device__ __forceinline__ void cp_async16(uint32_t saddr, const void* gptr) {
    asm volatile("cp.async.cg.shared.global [%0], [%1], 16;\n" :: "r"(saddr), "l"(gptr));
}
__device__ __forceinline__ void cp_async4(uint32_t saddr, const void* gptr) {
    asm volatile("cp.async.ca.shared.global [%0], [%1], 4;\n" :: "r"(saddr), "l"(gptr));
}
__device__ __forceinline__ void cp_commit() {
    asm volatile("cp.async.commit_group;\n");
}
template <int N>
__device__ __forceinline__ void cp_wait() {
    asm volatile("cp.async.wait_group %0;\n" :: "n"(N));
}

// Fast cos: Cody-Waite 2-term reduction by 2*pi, then MUFU cos (|r|<=pi).
__device__ __forceinline__ float fast_cos(float x) {
    const float INV_2PI   = 0.15915494309189535f;
    const float TWO_PI_HI = 6.28318548202514648f;
    const float TWO_PI_LO = -1.7484556e-7f;
    float k = rintf(x * INV_2PI);
    float r = fmaf(-k, TWO_PI_HI, x);
    r = fmaf(-k, TWO_PI_LO, r);
    return __cosf(r);
}

// Packed fp32x2 FMA (one issue, two FMAs).
__device__ __forceinline__ void ffma2(unsigned long long& acc,
                                      unsigned long long a,
                                      unsigned long long b) {
    asm("fma.rn.f32x2 %0, %1, %2, %3;" : "=l"(acc) : "l"(a), "l"(b), "l"(acc));
}
__device__ __forceinline__ float unpack_add(unsigned long long v) {
    unsigned lo, hi;
    asm("mov.b64 {%0,%1}, %2;" : "=r"(lo), "=r"(hi) : "l"(v));
    return __uint_as_float(lo) + __uint_as_float(hi);
}

// Double-buffered pipeline:
//   stage(t+1) via cp.async  ||  compute(t) from the other smem buffer
// Scalars (idx/mask) prefetched at depth 2 so the idx->gather dependency
// is hidden under compute as well.
__global__ __launch_bounds__(TILE, 4) void kde_time_encoder_kernel(
    const float* __restrict__ t_diff,
    const int* __restrict__ kde_idx,
    const int* __restrict__ kde_mask,
    const float* __restrict__ kde_table,
    const float* __restrict__ W_proj,
    const float* __restrict__ b_proj,
    const float* __restrict__ W_fb,
    const float* __restrict__ b_fb,
    float* __restrict__ out,
    int n)
{
    __shared__ __align__(16) float sk[2][TILE * RKHS];  // 2 x 10 KB
    __shared__ float st[2][TILE];
    __shared__ int   smk[2][TILE];

    const int tid   = threadIdx.x;
    const int lane  = tid & 31;
    const int wid   = tid >> 5;
    const int obase = lane * 4;

    // Pre-pack this lane's weights: wp[j][i] = (w_j[2i], w_j[2i+1]).
    unsigned long long wp[4][RKHS / 2];
    unsigned long long bpp[4];
    float wf[4], bf[4];
#pragma unroll
    for (int j = 0; j < 4; j++) {
        const float* wrow = W_proj + (obase + j) * RKHS;
#pragma unroll
        for (int i = 0; i < RKHS / 2; i++) {
            unsigned lo = __float_as_uint(wrow[2 * i]);
            unsigned hi = __float_as_uint(wrow[2 * i + 1]);
            wp[j][i] = (unsigned long long)lo | ((unsigned long long)hi << 32);
        }
        bpp[j] = (unsigned long long)__float_as_uint(b_proj[obase + j]);
        wf[j] = W_fb[obase + j];
        bf[j] = b_fb[obase + j];
    }

    const int ntiles = (n + TILE - 1) / TILE;
    const int stride = gridDim.x;
    const int tile0  = blockIdx.x;

    // Stage helper (inlined manually below via lambda-free macro-ish code):
    // writes mask (from reg), t (cp.async 4B), kv (5x cp.async 16B), commits.
    auto stage = [&](int buf, int tile, int m, int idx) {
        const int row = tile * TILE + tid;
        smk[buf][tid] = (row < n) ? m : 0;
        if (row < n) {
            cp_async4((uint32_t)__cvta_generic_to_shared(&st[buf][tid]),
                      t_diff + row);
            if (m) {
                const float* g = kde_table + (size_t)idx * RKHS;
                uint32_t s = (uint32_t)__cvta_generic_to_shared(sk[buf] + tid * RKHS);
#pragma unroll
                for (int q = 0; q < 5; q++)
                    cp_async16(s + 16u * q, g + 4 * q);
            }
        }
        cp_commit();   // every thread commits exactly one group per stage
    };

    // Scalar loader for a tile (depth-2 prefetch target).
    auto load_scalars = [&](int tile, int& m, int& idx) {
        m = 0; idx = 0;
        if (tile < ntiles) {
            const int row = tile * TILE + tid;
            if (row < n) {
                m   = kde_mask[row];
                idx = kde_idx[row];
            }
        }
    };

    // ---- Prologue ----
    if (tile0 >= ntiles) return;   // block-uniform
    int m_cur, idx_cur;
    load_scalars(tile0, m_cur, idx_cur);          // one exposed LDG latency
    stage(0, tile0, m_cur, idx_cur);              // group for buf0
    int m_nxt, idx_nxt;
    load_scalars(tile0 + stride, m_nxt, idx_nxt); // depth-2 scalar prefetch

    int cur = 0;
    for (int tile = tile0; tile < ntiles; tile += stride) {
        const int nxt = tile + stride;
        const bool has_next = nxt < ntiles;

        if (has_next) {
            stage(cur ^ 1, nxt, m_nxt, idx_nxt);          // async fill other buf
            load_scalars(nxt + stride, m_nxt, idx_nxt);   // LDGs hidden under compute
            cp_wait<1>();                                 // buf[cur]'s group done
        } else {
            cp_wait<0>();
        }
        __syncthreads();   // cp.async data visible block-wide

        // ---- compute tile from buf[cur] ----
        const int base  = tile * TILE;
        const int nrows = min(TILE, n - base);
        for (int r = wid; r < nrows; r += 4) {
            float4 res;
            if (smk[cur][r]) {                 // warp-uniform branch
                const ulonglong2* kk =
                    reinterpret_cast<const ulonglong2*>(sk[cur] + r * RKHS);
                unsigned long long a0 = bpp[0], a1 = bpp[1], a2 = bpp[2], a3 = bpp[3];
#pragma unroll
                for (int q = 0; q < 5; q++) {
                    ulonglong2 kp = kk[q];     // LDS.128 broadcast, pre-packed pairs
                    ffma2(a0, kp.x, wp[0][2 * q]);
                    ffma2(a1, kp.x, wp[1][2 * q]);
                    ffma2(a2, kp.x, wp[2][2 * q]);
                    ffma2(a3, kp.x, wp[3][2 * q]);
                    ffma2(a0, kp.y, wp[0][2 * q + 1]);
                    ffma2(a1, kp.y, wp[1][2 * q + 1]);
                    ffma2(a2, kp.y, wp[2][2 * q + 1]);
                    ffma2(a3, kp.y, wp[3][2 * q + 1]);
                }
                res.x = unpack_add(a0);
                res.y = unpack_add(a1);
                res.z = unpack_add(a2);
                res.w = unpack_add(a3);
            } else {
                float t = st[cur][r];
                res.x = fast_cos(fmaf(t, wf[0], bf[0]));
                res.y = fast_cos(fmaf(t, wf[1], bf[1]));
                res.z = fast_cos(fmaf(t, wf[2], bf[2]));
                res.w = fast_cos(fmaf(t, wf[3], bf[3]));
            }
            __stcs(reinterpret_cast<float4*>(out + (size_t)(base + r) * OUTD) + lane, res);
        }
        __syncthreads();   // all readers done before buf[cur] is restaged
        cur ^= 1;
    }
}

extern "C" void kernel_launch(void* const* d_in, const int* in_sizes, int n_in,
                              void* d_out, int out_size)
{
    // metadata order: src, dst, t_diff, kde_idx, kde_mask, kde_table,
    //                 W_proj, b_proj, W_fb, b_fb
    const float* t_diff    = (const float*)d_in[2];
    const int*   kde_idx   = (const int*)d_in[3];
    const int*   kde_mask  = (const int*)d_in[4];
    const float* kde_table = (const float*)d_in[5];
    const float* W_proj    = (const float*)d_in[6];
    const float* b_proj    = (const float*)d_in[7];
    const float* W_fb      = (const float*)d_in[8];
    const float* b_fb      = (const float*)d_in[9];
    float*       out       = (float*)d_out;

    const int n = in_sizes[2];  // BATCH

    // 4 resident blocks/SM x 148 SMs = 592 persistent blocks; ~13 tiles each.
    kde_time_encoder_kernel<<<592, TILE>>>(
        t_diff, kde_idx, kde_mask, kde_table, W_proj, b_proj, W_fb, b_fb, out, n);
}